// round 11
// baseline (speedup 1.0000x reference)
#include <cuda_runtime.h>
#include <cstdint>

// FieldAwareInteractionLayer:
//   X:     int32  [4096, 39]
//   table: f32    [100000, 39, 16]
//   out:   f32    [4096, 741, 16]
//   out[b, p, :] = table[X[b,iu[p]], ju[p], :] * table[X[b,ju[p]], iu[p], :]
//
// R10 analysis: byte count is at its floor (~475 MB, L2 captures all reuse a
// 126MB cache can). Remaining lever is DRAM efficiency: the "right" gather
// stream is ~194MB of scattered 64B segments. This version stages all 39
// table rows per batch into SMEM via fully-sequential 2.4KB row copies
// (same bytes, perfect DRAM locality), then computes every pair from SMEM:
//   out[pair(i,j)] = s_tile[i][field j] * s_tile[j][field i]
// SMEM pitch 157 float4/row -> compute-phase LDS is bank-conflict-free.

#define FIELDS   39
#define EMB      16
#define PAIRS    741                   // 39*38/2
#define ROW_F4   (FIELDS * EMB / 4)    // 156 float4 per table row
#define PITCH_F4 157                   // padded pitch (bank-conflict-free)
#define OUT_C32  (PAIRS * 2)           // 1482 32-byte chunks per batch row
#define STAGE_C32 (FIELDS * (ROW_F4 / 2))  // 39*78 = 3042 staging 32B chunks
#define THREADS  256
#define SMEM_BYTES (FIELDS * PITCH_F4 * 16)   // 97,968 B

// 256-bit global load, evict_last policy (table has cross-batch L2 reuse).
__device__ __forceinline__ void ldg_el_256(const float4* p, float4& a, float4& b)
{
    unsigned r0, r1, r2, r3, r4, r5, r6, r7;
    asm volatile(
        "ld.global.nc.L2::evict_last.v8.b32 {%0,%1,%2,%3,%4,%5,%6,%7}, [%8];"
        : "=r"(r0), "=r"(r1), "=r"(r2), "=r"(r3),
          "=r"(r4), "=r"(r5), "=r"(r6), "=r"(r7)
        : "l"(p));
    a.x = __uint_as_float(r0); a.y = __uint_as_float(r1);
    a.z = __uint_as_float(r2); a.w = __uint_as_float(r3);
    b.x = __uint_as_float(r4); b.y = __uint_as_float(r5);
    b.z = __uint_as_float(r6); b.w = __uint_as_float(r7);
}

__device__ __forceinline__ void stg_streaming(float4* p, float4 v)
{
    asm volatile("st.global.cs.v4.f32 [%0], {%1,%2,%3,%4};"
                 :: "l"(p), "f"(v.x), "f"(v.y), "f"(v.z), "f"(v.w)
                 : "memory");
}

__global__ void __launch_bounds__(THREADS)
ffm_interact_kernel(const int* __restrict__ X,
                    const float4* __restrict__ table,
                    float4* __restrict__ out)
{
    extern __shared__ float4 s_tile[];            // [FIELDS][PITCH_F4]
    __shared__ int            s_x[FIELDS];
    __shared__ unsigned short s_pair[PAIRS];

    const int b   = blockIdx.x;
    const int tid = threadIdx.x;

    if (tid < FIELDS)
        s_x[tid] = X[b * FIELDS + tid];
    __syncthreads();

    // ---- Stage phase: copy 39 full table rows, fully sequential reads. ----
    // chunk c covers 32B: row i = c/78, offset k = c%78 (in 32B units).
    #pragma unroll 4
    for (int c = tid; c < STAGE_C32; c += THREADS) {
        const int i = c / (ROW_F4 / 2);
        const int k = c - i * (ROW_F4 / 2);
        float4 a, d;
        ldg_el_256(&table[(size_t)s_x[i] * ROW_F4 + k * 2], a, d);
        s_tile[i * PITCH_F4 + k * 2]     = a;
        s_tile[i * PITCH_F4 + k * 2 + 1] = d;
    }

    // Build pair table (independent of staging; distinct smem region).
    for (int p = tid; p < PAIRS; p += THREADS) {
        int i = 0, rem = p;
        while (rem >= (FIELDS - 1 - i)) { rem -= (FIELDS - 1 - i); ++i; }
        int j = i + 1 + rem;
        s_pair[p] = (unsigned short)((i << 8) | j);
    }
    __syncthreads();

    // ---- Compute phase: products from SMEM, streaming stores. ----
    float4* o = out + (size_t)b * (PAIRS * 4);

    #pragma unroll 3
    for (int idx = tid; idx < OUT_C32; idx += THREADS) {
        const int p = idx >> 1;
        const int h = idx & 1;                     // 32B half of the segment
        const int pr = s_pair[p];
        const int i = pr >> 8;
        const int j = pr & 0xFF;

        const float4 L0 = s_tile[i * PITCH_F4 + j * 4 + h * 2];
        const float4 L1 = s_tile[i * PITCH_F4 + j * 4 + h * 2 + 1];
        const float4 R0 = s_tile[j * PITCH_F4 + i * 4 + h * 2];
        const float4 R1 = s_tile[j * PITCH_F4 + i * 4 + h * 2 + 1];

        float4 r0, r1;
        r0.x = L0.x * R0.x; r0.y = L0.y * R0.y;
        r0.z = L0.z * R0.z; r0.w = L0.w * R0.w;
        r1.x = L1.x * R1.x; r1.y = L1.y * R1.y;
        r1.z = L1.z * R1.z; r1.w = L1.w * R1.w;

        stg_streaming(&o[idx * 2],     r0);
        stg_streaming(&o[idx * 2 + 1], r1);
    }
}

extern "C" void kernel_launch(void* const* d_in, const int* in_sizes, int n_in,
                              void* d_out, int out_size)
{
    const int*    X     = (const int*)d_in[0];        // [4096, 39] int32
    const float4* table = (const float4*)d_in[1];     // [100000, 39, 16] f32
    float4*       out   = (float4*)d_out;             // [4096, 741, 16] f32

    const int batch = in_sizes[0] / FIELDS;           // 4096

    // Opt-in to >48KB dynamic smem (attribute set, not an allocation;
    // idempotent and executes immediately even under graph capture).
    cudaFuncSetAttribute(ffm_interact_kernel,
                         cudaFuncAttributeMaxDynamicSharedMemorySize,
                         SMEM_BYTES);

    ffm_interact_kernel<<<batch, THREADS, SMEM_BYTES>>>(X, table, out);
}

// round 16
// speedup vs baseline: 1.8810x; 1.8810x over previous
#include <cuda_runtime.h>
#include <cstdint>

// FieldAwareInteractionLayer:
//   X:     int32  [4096, 39]
//   table: f32    [100000, 39, 16]
//   out:   f32    [4096, 741, 16]
//   out[b, p, :] = table[X[b,iu[p]], ju[p], :] * table[X[b,ju[p]], iu[p], :]
//
// Staged-tile design (R13), with a hang-proof mbarrier protocol (R15):
// each of the 39 staging threads performs its OWN arrive.expect_tx(2496)
// immediately before its OWN cp.async.bulk, so the barrier tx-count can
// never go transiently negative in any interleaving. Barrier init count=39.
// Reads are fully-sequential 2.5 KB bursts (97 KB in flight per CTA);
// compute phase is bank-conflict-free LDS (pitch 157 float4) + evict-first
// streaming stores.

#define FIELDS    39
#define EMB       16
#define PAIRS     741                    // 39*38/2
#define ROW_F4    156                    // float4 per table row
#define ROW_BYTES (ROW_F4 * 16)          // 2496
#define PITCH_F4  157                    // padded pitch (conflict-free)
#define OUT_C32   (PAIRS * 2)            // 1482 32-byte chunks per batch row
#define THREADS   256
#define SMEM_TILE_BYTES (FIELDS * PITCH_F4 * 16)   // 97,968

__device__ __forceinline__ unsigned smem_u32(const void* p)
{
    unsigned a;
    asm("{ .reg .u64 t; cvta.to.shared.u64 t, %1; cvt.u32.u64 %0, t; }"
        : "=r"(a) : "l"(p));
    return a;
}

__device__ __forceinline__ void stg_streaming(float4* p, float4 v)
{
    asm volatile("st.global.cs.v4.f32 [%0], {%1,%2,%3,%4};"
                 :: "l"(p), "f"(v.x), "f"(v.y), "f"(v.z), "f"(v.w)
                 : "memory");
}

__global__ void __launch_bounds__(THREADS)
ffm_interact_kernel(const int* __restrict__ X,
                    const float* __restrict__ table,
                    float4* __restrict__ out)
{
    extern __shared__ float4 s_tile[];               // [FIELDS][PITCH_F4]
    __shared__ unsigned short s_pair[PAIRS];
    __shared__ __align__(8) unsigned long long s_mbar;

    const int b   = blockIdx.x;
    const int tid = threadIdx.x;
    const unsigned mbar = smem_u32(&s_mbar);

    if (tid == 0) {
        asm volatile("mbarrier.init.shared.b64 [%0], %1;"
                     :: "r"(mbar), "r"((unsigned)FIELDS) : "memory");
    }
    __syncthreads();   // barrier init visible to all staging threads

    // ---- Stage: per-thread expect_tx THEN bulk copy (tx-count >= 0 always).
    if (tid < FIELDS) {
        asm volatile("fence.proxy.async.shared::cta;" ::: "memory");
        const int row = X[b * FIELDS + tid];
        const float* src = table + (size_t)row * (ROW_F4 * 4);
        const unsigned dst = smem_u32(s_tile) + tid * (PITCH_F4 * 16);
        asm volatile("mbarrier.arrive.expect_tx.shared.b64 _, [%0], %1;"
                     :: "r"(mbar), "r"((unsigned)ROW_BYTES) : "memory");
        asm volatile(
            "cp.async.bulk.shared::cta.global.mbarrier::complete_tx::bytes "
            "[%0], [%1], %2, [%3];"
            :: "r"(dst), "l"(src), "r"((unsigned)ROW_BYTES), "r"(mbar)
            : "memory");
    }

    // ---- Pair table build overlaps the copy latency. ----
    for (int p = tid; p < PAIRS; p += THREADS) {
        int i = 0, rem = p;
        while (rem >= (FIELDS - 1 - i)) { rem -= (FIELDS - 1 - i); ++i; }
        int j = i + 1 + rem;
        s_pair[p] = (unsigned short)((i << 8) | j);
    }
    __syncthreads();

    // ---- Wait for 39 arrivals + 97,344 staged bytes (phase 0 -> 1). ----
    asm volatile(
        "{\n\t"
        ".reg .pred P;\n\t"
        "WAIT_%=:\n\t"
        "mbarrier.try_wait.parity.acquire.cta.shared::cta.b64 P, [%0], 0, 0x989680;\n\t"
        "@P bra.uni DONE_%=;\n\t"
        "bra.uni WAIT_%=;\n\t"
        "DONE_%=:\n\t"
        "}"
        :: "r"(mbar) : "memory");

    // ---- Compute: products from SMEM, streaming stores. ----
    float4* o = out + (size_t)b * (PAIRS * 4);

    #pragma unroll 3
    for (int idx = tid; idx < OUT_C32; idx += THREADS) {
        const int p = idx >> 1;
        const int h = idx & 1;                       // 32B half of the 64B seg
        const int pr = s_pair[p];
        const int i = pr >> 8;
        const int j = pr & 0xFF;

        // left  = tile[i][field j], right = tile[j][field i]
        const float4 L0 = s_tile[i * PITCH_F4 + j * 4 + h * 2];
        const float4 L1 = s_tile[i * PITCH_F4 + j * 4 + h * 2 + 1];
        const float4 R0 = s_tile[j * PITCH_F4 + i * 4 + h * 2];
        const float4 R1 = s_tile[j * PITCH_F4 + i * 4 + h * 2 + 1];

        float4 r0, r1;
        r0.x = L0.x * R0.x; r0.y = L0.y * R0.y;
        r0.z = L0.z * R0.z; r0.w = L0.w * R0.w;
        r1.x = L1.x * R1.x; r1.y = L1.y * R1.y;
        r1.z = L1.z * R1.z; r1.w = L1.w * R1.w;

        stg_streaming(&o[idx * 2],     r0);
        stg_streaming(&o[idx * 2 + 1], r1);
    }
}

extern "C" void kernel_launch(void* const* d_in, const int* in_sizes, int n_in,
                              void* d_out, int out_size)
{
    const int*   X     = (const int*)d_in[0];         // [4096, 39] int32
    const float* table = (const float*)d_in[1];       // [100000, 39, 16] f32
    float4*      out   = (float4*)d_out;              // [4096, 741, 16] f32

    const int batch = in_sizes[0] / FIELDS;           // 4096

    // Attribute set (not an allocation); executes immediately, capture-safe.
    cudaFuncSetAttribute(ffm_interact_kernel,
                         cudaFuncAttributeMaxDynamicSharedMemorySize,
                         SMEM_TILE_BYTES);

    ffm_interact_kernel<<<batch, THREADS, SMEM_TILE_BYTES>>>(X, table, out);
}